// round 12
// baseline (speedup 1.0000x reference)
#include <cuda_runtime.h>
#include <cuda_bf16.h>
#include <cuda_fp16.h>
#include <cstdint>

// Problem constants (N=170000, E=1200000, IN=HID=128, OUT=40)
#define NN 170000
#define EE 1200000
#define CIN 128
#define CH 128
#define COUT 40
#define SCAN_B 512
#define NBLK ((NN + SCAN_B - 1) / SCAN_B)   // 333
#define KS 136   // smem k-stride (bf16 elems), padded for conflict-free LDSM

// Scratch (static __device__ arrays per allocation rules)
__device__ __half g_h1[(size_t)NN * CH];     // x @ W1 (UNscaled), fp16
__device__ __half g_h[(size_t)NN * CH];      // relu'd hidden, fp16
__device__ __half g_h2s[(size_t)NN * COUT];  // dis * (h @ W2), fp16
__device__ float g_dis[NN];
__device__ int g_cnt[NN];
__device__ int g_incl[NN];
__device__ int g_start[NN];
__device__ int g_cur[NN];
__device__ volatile int g_flag[NBLK];
__device__ volatile int g_aggv[NBLK];
__device__ volatile int g_pref[NBLK];
__device__ int2 g_epay[EE];  // per-edge payload {src, bits(dis[src])}, dst-grouped

// ---------------------------------------------------------------------------
__global__ void k_zero(int n) {
    int i = blockIdx.x * blockDim.x + threadIdx.x;
    if (i < n) { g_cnt[i] = 0; g_cur[i] = 0; }
    if (i < NBLK) g_flag[i] = 0;
}

__global__ void k_hist(const int* __restrict__ dst, int e) {
    int i = blockIdx.x * blockDim.x + threadIdx.x;
    if (i < e) atomicAdd(&g_cnt[dst[i]], 1);
}

// Single-pass inclusive scan of g_cnt (decoupled lookback) + fused dis.
__global__ void k_scanDL(int n) {
    __shared__ int sm[SCAN_B];
    __shared__ int s_excl;
    const int t = threadIdx.x, bid = blockIdx.x;
    const int i = bid * SCAN_B + t;
    int v = (i < n) ? g_cnt[i] : 0;
    sm[t] = v;
    __syncthreads();
#pragma unroll
    for (int off = 1; off < SCAN_B; off <<= 1) {
        int u = (t >= off) ? sm[t - off] : 0;
        __syncthreads();
        sm[t] += u;
        __syncthreads();
    }
    const int incl_local = sm[t];
    const int agg = sm[SCAN_B - 1];

    if (bid == 0) {
        if (t == 0) {
            g_pref[0] = agg;
            __threadfence();
            g_flag[0] = 2;
            s_excl = 0;
        }
    } else {
        if (t == 0) {
            g_aggv[bid] = agg;
            __threadfence();
            g_flag[bid] = 1;
        }
        if (t < 32) {
            int excl = 0;
            for (int base = bid - 1; base >= 0; base -= 32) {
                int j = base - t;
                int f = 0, a = 0;
                if (j >= 0) {
                    while ((f = g_flag[j]) == 0) {}
                    a = (f == 2) ? g_pref[j] : g_aggv[j];
                }
                unsigned done = __ballot_sync(0xffffffffu, (j >= 0) && (f == 2));
                int contrib;
                if (done) {
                    int firstLane = __ffs(done) - 1;
                    contrib = (t <= firstLane) ? a : 0;
                } else {
                    contrib = (j >= 0) ? a : 0;
                }
#pragma unroll
                for (int o = 16; o; o >>= 1) contrib += __shfl_xor_sync(0xffffffffu, contrib, o);
                excl += contrib;
                if (done) break;
            }
            if (t == 0) {
                g_pref[bid] = excl + agg;
                __threadfence();
                g_flag[bid] = 2;
                s_excl = excl;
            }
        }
    }
    __syncthreads();
    const int excl = s_excl;
    if (i < n) {
        int incl = incl_local + excl;
        g_incl[i] = incl;
        g_start[i] = incl - v;
        g_dis[i] = rsqrtf((float)(v + 1));  // +1 self-loop
    }
}

// scatter with fused payload {src, dis[src]} (dis ready: scanDL precedes)
__global__ void k_scatter(const int* __restrict__ src, const int* __restrict__ dst, int e) {
    int i = blockIdx.x * blockDim.x + threadIdx.x;
    if (i >= e) return;
    int d = dst[i];
    int s = src[i];
    float w = g_dis[s];
    int pos = atomicAdd(&g_cur[d], 1);
    g_epay[g_start[d] + pos] = make_int2(s, __float_as_int(w));
}

// ---------------------------------------------------------------------------
// bf16-split tensor-core GEMM: Y = (optionally dis[row] *) X[row,:128] @ W[:128,wcols]
__device__ __forceinline__ void ldsm_x4(uint32_t* r, uint32_t addr) {
    asm volatile("ldmatrix.sync.aligned.m8n8.x4.shared.b16 {%0,%1,%2,%3}, [%4];"
                 : "=r"(r[0]), "=r"(r[1]), "=r"(r[2]), "=r"(r[3]) : "r"(addr));
}
__device__ __forceinline__ void ldsm_x2(uint32_t* r, uint32_t addr) {
    asm volatile("ldmatrix.sync.aligned.m8n8.x2.shared.b16 {%0,%1}, [%2];"
                 : "=r"(r[0]), "=r"(r[1]) : "r"(addr));
}
__device__ __forceinline__ void mma_bf16(float* d, const uint32_t* a, const uint32_t* b) {
    asm volatile("mma.sync.aligned.m16n8k16.row.col.f32.bf16.bf16.f32 "
                 "{%0,%1,%2,%3}, {%4,%5,%6,%7}, {%8,%9}, {%0,%1,%2,%3};"
                 : "+f"(d[0]), "+f"(d[1]), "+f"(d[2]), "+f"(d[3])
                 : "r"(a[0]), "r"(a[1]), "r"(a[2]), "r"(a[3]), "r"(b[0]), "r"(b[1]));
}

template <int CO, bool SCALE, typename TIN>
__global__ void __launch_bounds__(256, 2)
k_mma(const TIN* __restrict__ X, const float* __restrict__ Wg, int wcols,
      __half* __restrict__ Y, int n) {
    extern __shared__ char smc[];
    __nv_bfloat16* Ahi = (__nv_bfloat16*)smc;
    __nv_bfloat16* Alo = Ahi + 64 * KS;
    __nv_bfloat16* Whi = Alo + 64 * KS;
    __nv_bfloat16* Wlo = Whi + CO * KS;

    const int t = threadIdx.x;
    const int row0 = blockIdx.x * 64;

    for (int idx = t; idx < 128 * CO; idx += 256) {
        int k = idx / CO, nn_ = idx % CO;
        float v = (nn_ < wcols) ? Wg[k * wcols + nn_] : 0.f;
        __nv_bfloat16 h = __float2bfloat16(v);
        __nv_bfloat16 l = __float2bfloat16(v - __bfloat162float(h));
        Whi[nn_ * KS + k] = h;
        Wlo[nn_ * KS + k] = l;
    }
    for (int idx = t; idx < 64 * 32; idx += 256) {
        int r = idx >> 5, c4 = idx & 31;
        int k = c4 * 4;
        float v0 = 0.f, v1 = 0.f, v2 = 0.f, v3 = 0.f;
        if (row0 + r < n) {
            if (sizeof(TIN) == 4) {
                float4 v = ((const float4*)((const float*)X + (size_t)(row0 + r) * 128))[c4];
                v0 = v.x; v1 = v.y; v2 = v.z; v3 = v.w;
            } else {
                uint2 raw = *(const uint2*)((const __half*)X + (size_t)(row0 + r) * 128 + k);
                float2 f0 = __half22float2(*(__half2*)&raw.x);
                float2 f1 = __half22float2(*(__half2*)&raw.y);
                v0 = f0.x; v1 = f0.y; v2 = f1.x; v3 = f1.y;
            }
        }
        __nv_bfloat16 h0 = __float2bfloat16(v0), h1 = __float2bfloat16(v1);
        __nv_bfloat16 h2 = __float2bfloat16(v2), h3 = __float2bfloat16(v3);
        __nv_bfloat16 l0 = __float2bfloat16(v0 - __bfloat162float(h0));
        __nv_bfloat16 l1 = __float2bfloat16(v1 - __bfloat162float(h1));
        __nv_bfloat16 l2 = __float2bfloat16(v2 - __bfloat162float(h2));
        __nv_bfloat16 l3 = __float2bfloat16(v3 - __bfloat162float(h3));
        *(__nv_bfloat162*)(Ahi + r * KS + k)     = __halves2bfloat162(h0, h1);
        *(__nv_bfloat162*)(Ahi + r * KS + k + 2) = __halves2bfloat162(h2, h3);
        *(__nv_bfloat162*)(Alo + r * KS + k)     = __halves2bfloat162(l0, l1);
        *(__nv_bfloat162*)(Alo + r * KS + k + 2) = __halves2bfloat162(l2, l3);
    }
    __syncthreads();

    const int w = t >> 5, lane = t & 31;
    const int wm = w & 1, wn = w >> 1;
    constexpr int NF = CO / 32;
    constexpr int WN = CO / 4;

    uint32_t sbase;
    asm("{ .reg .u64 tt; cvta.to.shared.u64 tt, %1; cvt.u32.u64 %0, tt; }"
        : "=r"(sbase) : "l"(smc));
    const uint32_t aHiB = sbase;
    const uint32_t aLoB = sbase + 64 * KS * 2;
    const uint32_t wHiB = sbase + 2 * 64 * KS * 2;
    const uint32_t wLoB = wHiB + CO * KS * 2;

    uint32_t aOff[2];
#pragma unroll
    for (int mf = 0; mf < 2; mf++) {
        int row = wm * 32 + mf * 16 + (lane & 15);
        aOff[mf] = (uint32_t)(row * KS + ((lane >> 4) << 3)) * 2;
    }
    uint32_t bOff[NF];
#pragma unroll
    for (int nf = 0; nf < NF; nf++) {
        int nr = wn * WN + nf * 8 + (lane & 7);
        bOff[nf] = (uint32_t)(nr * KS + (lane & 8)) * 2;
    }

    float acc[2][NF][4];
#pragma unroll
    for (int mf = 0; mf < 2; mf++)
#pragma unroll
        for (int nf = 0; nf < NF; nf++)
#pragma unroll
            for (int i = 0; i < 4; i++) acc[mf][nf][i] = 0.f;

#pragma unroll
    for (int ks = 0; ks < 8; ks++) {
        const uint32_t kb = ks * 16 * 2;
        uint32_t ah[2][4], al[2][4], bh[NF][2], bl[NF][2];
#pragma unroll
        for (int mf = 0; mf < 2; mf++) {
            ldsm_x4(ah[mf], aHiB + aOff[mf] + kb);
            ldsm_x4(al[mf], aLoB + aOff[mf] + kb);
        }
#pragma unroll
        for (int nf = 0; nf < NF; nf++) {
            ldsm_x2(bh[nf], wHiB + bOff[nf] + kb);
            ldsm_x2(bl[nf], wLoB + bOff[nf] + kb);
        }
#pragma unroll
        for (int mf = 0; mf < 2; mf++)
#pragma unroll
            for (int nf = 0; nf < NF; nf++) {
                mma_bf16(acc[mf][nf], ah[mf], bh[nf]);
                mma_bf16(acc[mf][nf], ah[mf], bl[nf]);
                mma_bf16(acc[mf][nf], al[mf], bh[nf]);
            }
    }

#pragma unroll
    for (int mf = 0; mf < 2; mf++) {
        int rowA = row0 + wm * 32 + mf * 16 + (lane >> 2);
        int rowB = rowA + 8;
        float dA = 1.f, dB = 1.f;
        if (SCALE) {
            dA = (rowA < n) ? g_dis[rowA] : 0.f;
            dB = (rowB < n) ? g_dis[rowB] : 0.f;
        }
#pragma unroll
        for (int nf = 0; nf < NF; nf++) {
            int col = wn * WN + nf * 8 + ((lane & 3) << 1);
            if (CO != 128 && col >= wcols) continue;
            if (rowA < n) {
                __half2 v = __floats2half2_rn(acc[mf][nf][0] * dA, acc[mf][nf][1] * dA);
                *(__half2*)(Y + (size_t)rowA * wcols + col) = v;
            }
            if (rowB < n) {
                __half2 v = __floats2half2_rn(acc[mf][nf][2] * dB, acc[mf][nf][3] * dB);
                *(__half2*)(Y + (size_t)rowB * wcols + col) = v;
            }
        }
    }
}

// ---------------------------------------------------------------------------
__device__ __forceinline__ void acc4w(float* acc, float w, uint2 raw) {
    float2 f0 = __half22float2(*(__half2*)&raw.x);
    float2 f1 = __half22float2(*(__half2*)&raw.y);
    acc[0] = fmaf(w, f0.x, acc[0]);
    acc[1] = fmaf(w, f0.y, acc[1]);
    acc[2] = fmaf(w, f1.x, acc[2]);
    acc[3] = fmaf(w, f1.y, acc[3]);
}
__device__ __forceinline__ void acc4(float* acc, uint2 raw) {
    float2 f0 = __half22float2(*(__half2*)&raw.x);
    float2 f1 = __half22float2(*(__half2*)&raw.y);
    acc[0] += f0.x; acc[1] += f0.y; acc[2] += f1.x; acc[3] += f1.y;
}

// Layer-1 aggregation: warp/node, 4 ch/lane; edge payload carries {src, dis}
// so the per-edge chain is payload (broadcast) -> row load (2 hops, not 3).
__global__ void k_aggA(const float* __restrict__ b1, int n) {
    int g = blockIdx.x * blockDim.x + threadIdx.x;
    int node = g >> 5, lane = g & 31;
    if (node >= n) return;
    int end = g_incl[node];
    int p = end - g_cnt[node];
    float acc[4] = {0.f, 0.f, 0.f, 0.f};
    for (; p + 8 <= end; p += 8) {
        int2 pay[8];
#pragma unroll
        for (int j = 0; j < 8; j++) pay[j] = g_epay[p + j];
        uint2 r[8];
#pragma unroll
        for (int j = 0; j < 8; j++)
            r[j] = *(const uint2*)(g_h1 + (size_t)pay[j].x * CH + lane * 4);
#pragma unroll
        for (int j = 0; j < 8; j++) acc4w(acc, __int_as_float(pay[j].y), r[j]);
    }
    for (; p < end; ++p) {
        int2 pay = g_epay[p];
        acc4w(acc, __int_as_float(pay.y),
              *(const uint2*)(g_h1 + (size_t)pay.x * CH + lane * 4));
    }
    float di = g_dis[node];
    acc4w(acc, di, *(const uint2*)(g_h1 + (size_t)node * CH + lane * 4));
    float4 b = ((const float4*)b1)[lane];
    float o0 = fmaxf(fmaf(di, acc[0], b.x), 0.f);
    float o1 = fmaxf(fmaf(di, acc[1], b.y), 0.f);
    float o2 = fmaxf(fmaf(di, acc[2], b.z), 0.f);
    float o3 = fmaxf(fmaf(di, acc[3], b.w), 0.f);
    uint2 outw;
    *(__half2*)&outw.x = __floats2half2_rn(o0, o1);
    *(__half2*)&outw.y = __floats2half2_rn(o2, o3);
    *(uint2*)(g_h + (size_t)node * CH + lane * 4) = outw;
}

// Layer-2 aggregation (h2s pre-scaled, fp16), fused self-loop+bias; fp32 out.
__global__ void k_aggB(const float* __restrict__ b2, float* __restrict__ out, int n) {
    int g = blockIdx.x * blockDim.x + threadIdx.x;
    int node = g / 10, l = g % 10;
    if (node >= n) return;
    int end = g_incl[node];
    int p = end - g_cnt[node];
    float acc[4] = {0.f, 0.f, 0.f, 0.f};
    for (; p + 4 <= end; p += 4) {
        int s0 = g_epay[p].x, s1 = g_epay[p + 1].x;
        int s2 = g_epay[p + 2].x, s3 = g_epay[p + 3].x;
        uint2 r0 = *(const uint2*)(g_h2s + (size_t)s0 * COUT + l * 4);
        uint2 r1 = *(const uint2*)(g_h2s + (size_t)s1 * COUT + l * 4);
        uint2 r2 = *(const uint2*)(g_h2s + (size_t)s2 * COUT + l * 4);
        uint2 r3 = *(const uint2*)(g_h2s + (size_t)s3 * COUT + l * 4);
        acc4(acc, r0); acc4(acc, r1); acc4(acc, r2); acc4(acc, r3);
    }
    for (; p < end; ++p) {
        int s = g_epay[p].x;
        acc4(acc, *(const uint2*)(g_h2s + (size_t)s * COUT + l * 4));
    }
    acc4(acc, *(const uint2*)(g_h2s + (size_t)node * COUT + l * 4));
    float di = g_dis[node];
    float4 b = *(const float4*)(b2 + l * 4);
    float4 r;
    r.x = fmaf(di, acc[0], b.x);
    r.y = fmaf(di, acc[1], b.y);
    r.z = fmaf(di, acc[2], b.z);
    r.w = fmaf(di, acc[3], b.w);
    *(float4*)(out + (size_t)node * COUT + l * 4) = r;
}

// ---------------------------------------------------------------------------
extern "C" void kernel_launch(void* const* d_in, const int* in_sizes, int n_in,
                              void* d_out, int out_size) {
    const float* x  = (const float*)d_in[0];
    const float* W1 = (const float*)d_in[1];
    const float* b1 = (const float*)d_in[2];
    const float* W2 = (const float*)d_in[3];
    const float* b2 = (const float*)d_in[4];
    const int* edge = (const int*)d_in[5];

    const int n = in_sizes[0] / CIN;
    const int e = in_sizes[5] / 2;
    const int* src = edge;
    const int* dst = edge + e;
    float* out = (float*)d_out;

    __half *p_h1 = nullptr, *p_h = nullptr, *p_h2s = nullptr;
    cudaGetSymbolAddress((void**)&p_h1, g_h1);
    cudaGetSymbolAddress((void**)&p_h, g_h);
    cudaGetSymbolAddress((void**)&p_h2s, g_h2s);

    const int smem1 = (2 * 64 * KS + 2 * 128 * KS) * 2;  // 104448 B
    const int smem2 = (2 * 64 * KS + 2 * 64 * KS) * 2;   // 69632 B
    cudaFuncSetAttribute(k_mma<128, false, float>, cudaFuncAttributeMaxDynamicSharedMemorySize, smem1);
    cudaFuncSetAttribute(k_mma<64, true, __half>,  cudaFuncAttributeMaxDynamicSharedMemorySize, smem2);

    static cudaStream_t s1 = nullptr, s2 = nullptr;
    static cudaEvent_t evFork = nullptr, evJoin = nullptr, evDone = nullptr;
    if (s1 == nullptr) {
        cudaStreamCreateWithFlags(&s1, cudaStreamNonBlocking);
        cudaStreamCreateWithFlags(&s2, cudaStreamNonBlocking);
        cudaEventCreateWithFlags(&evFork, cudaEventDisableTiming);
        cudaEventCreateWithFlags(&evJoin, cudaEventDisableTiming);
        cudaEventCreateWithFlags(&evDone, cudaEventDisableTiming);
    }

    // Fork into s1 (GEMM chain) and s2 (CSR).
    cudaEventRecord(evFork, 0);
    cudaStreamWaitEvent(s1, evFork, 0);
    cudaStreamWaitEvent(s2, evFork, 0);

    // CSR branch (latency-bound; overlaps with GEMM1)
    k_zero<<<(n + 255) / 256, 256, 0, s2>>>(n);
    k_hist<<<(e + 255) / 256, 256, 0, s2>>>(dst, e);
    k_scanDL<<<NBLK, SCAN_B, 0, s2>>>(n);
    k_scatter<<<(e + 255) / 256, 256, 0, s2>>>(src, dst, e);
    cudaEventRecord(evJoin, s2);

    // GEMM1 branch
    k_mma<128, false, float><<<(n + 63) / 64, 256, smem1, s1>>>(x, W1, 128, p_h1, n);

    // Join: aggregation needs CSR + dis + h1
    cudaStreamWaitEvent(s1, evJoin, 0);
    k_aggA<<<(int)(((size_t)n * 32 + 255) / 256), 256, 0, s1>>>(b1, n);

    // layer 2 (GEMM first: aggregate only 40 channels)
    k_mma<64, true, __half><<<(n + 63) / 64, 256, smem2, s1>>>(p_h, W2, COUT, p_h2s, n);
    k_aggB<<<(int)(((size_t)n * 10 + 319) / 320), 320, 0, s1>>>(b2, out, n);

    // Join back to the launch stream.
    cudaEventRecord(evDone, s1);
    cudaStreamWaitEvent(0, evDone, 0);
}

// round 13
// speedup vs baseline: 1.6736x; 1.6736x over previous
#include <cuda_runtime.h>
#include <cuda_bf16.h>
#include <cuda_fp16.h>
#include <cstdint>

// Problem constants (N=170000, E=1200000, IN=HID=128, OUT=40)
#define NN 170000
#define EE 1200000
#define CIN 128
#define CH 128
#define COUT 40
#define SCAN_B 512
#define NBLK ((NN + SCAN_B - 1) / SCAN_B)   // 333
#define KS 136   // smem k-stride (halves), padded for conflict-free LDSM

// Scratch (static __device__ arrays per allocation rules)
__device__ __half g_h1[(size_t)NN * CH];     // x @ W1 (UNscaled), fp16
__device__ __half g_h[(size_t)NN * CH];      // relu'd hidden, fp16
__device__ __half g_h2s[(size_t)NN * COUT];  // dis * (h @ W2), fp16
__device__ __align__(16) __half g_w1h[128 * KS];  // W1^T fp16, padded rows
__device__ __align__(16) __half g_w2h[64 * KS];   // W2^T fp16 (zero-pad cols>=40)
__device__ float g_dis[NN];
__device__ int g_cnt[NN];
__device__ int g_incl[NN];
__device__ int g_start[NN];
__device__ int g_cur[NN];
__device__ volatile int g_flag[NBLK];
__device__ volatile int g_aggv[NBLK];
__device__ volatile int g_pref[NBLK];
__device__ int g_csrc[EE];   // edge srcs grouped by dst

// ---------------------------------------------------------------------------
__global__ void k_zero(int n) {
    int i = blockIdx.x * blockDim.x + threadIdx.x;
    if (i < n) { g_cnt[i] = 0; g_cur[i] = 0; }
    if (i < NBLK) g_flag[i] = 0;
}

__global__ void k_hist(const int* __restrict__ dst, int e) {
    int i = blockIdx.x * blockDim.x + threadIdx.x;
    if (i < e) atomicAdd(&g_cnt[dst[i]], 1);
}

// W1/W2 -> transposed fp16 buffers in the exact smem layout (n-major, KS stride)
__global__ void k_wconv(const float* __restrict__ W1, const float* __restrict__ W2) {
    int i = blockIdx.x * blockDim.x + threadIdx.x;
    if (i < 128 * 128) {
        int nn = i >> 7, k = i & 127;
        g_w1h[nn * KS + k] = __float2half(W1[k * 128 + nn]);
    } else if (i < 128 * 128 + 64 * 128) {
        int j = i - 128 * 128;
        int nn = j >> 7, k = j & 127;
        float v = (nn < COUT) ? W2[k * COUT + nn] : 0.f;
        g_w2h[nn * KS + k] = __float2half(v);
    }
}

// Single-pass inclusive scan of g_cnt (decoupled lookback) + fused dis.
__global__ void k_scanDL(int n) {
    __shared__ int sm[SCAN_B];
    __shared__ int s_excl;
    const int t = threadIdx.x, bid = blockIdx.x;
    const int i = bid * SCAN_B + t;
    int v = (i < n) ? g_cnt[i] : 0;
    sm[t] = v;
    __syncthreads();
#pragma unroll
    for (int off = 1; off < SCAN_B; off <<= 1) {
        int u = (t >= off) ? sm[t - off] : 0;
        __syncthreads();
        sm[t] += u;
        __syncthreads();
    }
    const int incl_local = sm[t];
    const int agg = sm[SCAN_B - 1];

    if (bid == 0) {
        if (t == 0) {
            g_pref[0] = agg;
            __threadfence();
            g_flag[0] = 2;
            s_excl = 0;
        }
    } else {
        if (t == 0) {
            g_aggv[bid] = agg;
            __threadfence();
            g_flag[bid] = 1;
        }
        if (t < 32) {
            int excl = 0;
            for (int base = bid - 1; base >= 0; base -= 32) {
                int j = base - t;
                int f = 0, a = 0;
                if (j >= 0) {
                    while ((f = g_flag[j]) == 0) {}
                    a = (f == 2) ? g_pref[j] : g_aggv[j];
                }
                unsigned done = __ballot_sync(0xffffffffu, (j >= 0) && (f == 2));
                int contrib;
                if (done) {
                    int firstLane = __ffs(done) - 1;
                    contrib = (t <= firstLane) ? a : 0;
                } else {
                    contrib = (j >= 0) ? a : 0;
                }
#pragma unroll
                for (int o = 16; o; o >>= 1) contrib += __shfl_xor_sync(0xffffffffu, contrib, o);
                excl += contrib;
                if (done) break;
            }
            if (t == 0) {
                g_pref[bid] = excl + agg;
                __threadfence();
                g_flag[bid] = 2;
                s_excl = excl;
            }
        }
    }
    __syncthreads();
    const int excl = s_excl;
    if (i < n) {
        int incl = incl_local + excl;
        g_incl[i] = incl;
        g_start[i] = incl - v;
        g_dis[i] = rsqrtf((float)(v + 1));  // +1 self-loop
    }
}

__global__ void k_scatter(const int* __restrict__ src, const int* __restrict__ dst, int e) {
    int i = blockIdx.x * blockDim.x + threadIdx.x;
    if (i >= e) return;
    int d = dst[i];
    int pos = atomicAdd(&g_cur[d], 1);
    g_csrc[g_start[d] + pos] = src[i];
}

// ---------------------------------------------------------------------------
// fp16 single-pass tensor-core GEMM:
//   Y(fp16) = (optionally dis[row] *) X[row,:128] @ W[:128, wcols]
__device__ __forceinline__ void ldsm_x4(uint32_t* r, uint32_t addr) {
    asm volatile("ldmatrix.sync.aligned.m8n8.x4.shared.b16 {%0,%1,%2,%3}, [%4];"
                 : "=r"(r[0]), "=r"(r[1]), "=r"(r[2]), "=r"(r[3]) : "r"(addr));
}
__device__ __forceinline__ void ldsm_x2(uint32_t* r, uint32_t addr) {
    asm volatile("ldmatrix.sync.aligned.m8n8.x2.shared.b16 {%0,%1}, [%2];"
                 : "=r"(r[0]), "=r"(r[1]) : "r"(addr));
}
__device__ __forceinline__ void mma_f16(float* d, const uint32_t* a, const uint32_t* b) {
    asm volatile("mma.sync.aligned.m16n8k16.row.col.f32.f16.f16.f32 "
                 "{%0,%1,%2,%3}, {%4,%5,%6,%7}, {%8,%9}, {%0,%1,%2,%3};"
                 : "+f"(d[0]), "+f"(d[1]), "+f"(d[2]), "+f"(d[3])
                 : "r"(a[0]), "r"(a[1]), "r"(a[2]), "r"(a[3]), "r"(b[0]), "r"(b[1]));
}

template <int CO, bool SCALE, typename TIN>
__global__ void __launch_bounds__(256, (CO == 128) ? 4 : 6)
k_mma(const TIN* __restrict__ X, const __half* __restrict__ Wh, int wcols,
      __half* __restrict__ Y, int n) {
    extern __shared__ char smc[];
    __half* Ah = (__half*)smc;           // 64*KS
    __half* Ws = Ah + 64 * KS;           // CO*KS

    const int t = threadIdx.x;
    const int row0 = blockIdx.x * 64;

    // W copy from pre-converted global (pure uint4 copy; KS=136 = 17 x 8 halves)
    for (int idx = t; idx < CO * 17; idx += 256)
        ((uint4*)Ws)[idx] = ((const uint4*)Wh)[idx];

    // A tile
    if (sizeof(TIN) == 4) {
        // fp32 -> fp16 convert, 4 elems/thread/iter
        for (int idx = t; idx < 64 * 32; idx += 256) {
            int r = idx >> 5, c4 = idx & 31;
            float4 v = make_float4(0.f, 0.f, 0.f, 0.f);
            if (row0 + r < n)
                v = ((const float4*)((const float*)X + (size_t)(row0 + r) * 128))[c4];
            __half2 p0 = __floats2half2_rn(v.x, v.y);
            __half2 p1 = __floats2half2_rn(v.z, v.w);
            uint2 w;
            w.x = *(uint32_t*)&p0;
            w.y = *(uint32_t*)&p1;
            *(uint2*)(Ah + r * KS + c4 * 4) = w;
        }
    } else {
        // fp16 -> pure uint4 copy, 8 elems/thread/iter
        for (int idx = t; idx < 64 * 16; idx += 256) {
            int r = idx >> 4, c8 = idx & 15;
            uint4 v = make_uint4(0, 0, 0, 0);
            if (row0 + r < n)
                v = *(const uint4*)((const __half*)X + (size_t)(row0 + r) * 128 + c8 * 8);
            *(uint4*)(Ah + r * KS + c8 * 8) = v;
        }
    }
    __syncthreads();

    const int w = t >> 5, lane = t & 31;
    const int wm = w & 1, wn = w >> 1;          // 2(M) x 4(N)
    constexpr int NF = CO / 32;                 // 4 or 2
    constexpr int WN = CO / 4;                  // 32 or 16

    uint32_t sbase;
    asm("{ .reg .u64 tt; cvta.to.shared.u64 tt, %1; cvt.u32.u64 %0, tt; }"
        : "=r"(sbase) : "l"(smc));
    const uint32_t aB = sbase;
    const uint32_t wB = sbase + 64 * KS * 2;

    uint32_t aOff[2];
#pragma unroll
    for (int mf = 0; mf < 2; mf++) {
        int row = wm * 32 + mf * 16 + (lane & 15);
        aOff[mf] = (uint32_t)(row * KS + ((lane >> 4) << 3)) * 2;
    }
    uint32_t bOff[NF];
#pragma unroll
    for (int nf = 0; nf < NF; nf++) {
        int nr = wn * WN + nf * 8 + (lane & 7);
        bOff[nf] = (uint32_t)(nr * KS + (lane & 8)) * 2;
    }

    float acc[2][NF][4];
#pragma unroll
    for (int mf = 0; mf < 2; mf++)
#pragma unroll
        for (int nf = 0; nf < NF; nf++)
#pragma unroll
            for (int i = 0; i < 4; i++) acc[mf][nf][i] = 0.f;

#pragma unroll
    for (int ks = 0; ks < 8; ks++) {
        const uint32_t kb = ks * 16 * 2;
        uint32_t ah[2][4], bh[NF][2];
#pragma unroll
        for (int mf = 0; mf < 2; mf++) ldsm_x4(ah[mf], aB + aOff[mf] + kb);
#pragma unroll
        for (int nf = 0; nf < NF; nf++) ldsm_x2(bh[nf], wB + bOff[nf] + kb);
#pragma unroll
        for (int mf = 0; mf < 2; mf++)
#pragma unroll
            for (int nf = 0; nf < NF; nf++)
                mma_f16(acc[mf][nf], ah[mf], bh[nf]);
    }

#pragma unroll
    for (int mf = 0; mf < 2; mf++) {
        int rowA = row0 + wm * 32 + mf * 16 + (lane >> 2);
        int rowB = rowA + 8;
        float dA = 1.f, dB = 1.f;
        if (SCALE) {
            dA = (rowA < n) ? g_dis[rowA] : 0.f;
            dB = (rowB < n) ? g_dis[rowB] : 0.f;
        }
#pragma unroll
        for (int nf = 0; nf < NF; nf++) {
            int col = wn * WN + nf * 8 + ((lane & 3) << 1);
            if (CO != 128 && col >= wcols) continue;
            if (rowA < n) {
                __half2 v = __floats2half2_rn(acc[mf][nf][0] * dA, acc[mf][nf][1] * dA);
                *(__half2*)(Y + (size_t)rowA * wcols + col) = v;
            }
            if (rowB < n) {
                __half2 v = __floats2half2_rn(acc[mf][nf][2] * dB, acc[mf][nf][3] * dB);
                *(__half2*)(Y + (size_t)rowB * wcols + col) = v;
            }
        }
    }
}

// ---------------------------------------------------------------------------
__device__ __forceinline__ void acc4w(float* acc, float w, uint2 raw) {
    float2 f0 = __half22float2(*(__half2*)&raw.x);
    float2 f1 = __half22float2(*(__half2*)&raw.y);
    acc[0] = fmaf(w, f0.x, acc[0]);
    acc[1] = fmaf(w, f0.y, acc[1]);
    acc[2] = fmaf(w, f1.x, acc[2]);
    acc[3] = fmaf(w, f1.y, acc[3]);
}
__device__ __forceinline__ void acc4(float* acc, uint2 raw) {
    float2 f0 = __half22float2(*(__half2*)&raw.x);
    float2 f1 = __half22float2(*(__half2*)&raw.y);
    acc[0] += f0.x; acc[1] += f0.y; acc[2] += f1.x; acc[3] += f1.y;
}

// Layer-1 aggregation (round-10 form): warp/node, 4 ch/lane, unroll 8.
__global__ void k_aggA(const float* __restrict__ b1, int n) {
    int g = blockIdx.x * blockDim.x + threadIdx.x;
    int node = g >> 5, lane = g & 31;
    if (node >= n) return;
    int end = g_incl[node];
    int p = end - g_cnt[node];
    float acc[4] = {0.f, 0.f, 0.f, 0.f};
    for (; p + 8 <= end; p += 8) {
        int s[8];
#pragma unroll
        for (int j = 0; j < 8; j++) s[j] = g_csrc[p + j];
        float w[8];
#pragma unroll
        for (int j = 0; j < 8; j++) w[j] = g_dis[s[j]];
        uint2 r[8];
#pragma unroll
        for (int j = 0; j < 8; j++)
            r[j] = *(const uint2*)(g_h1 + (size_t)s[j] * CH + lane * 4);
#pragma unroll
        for (int j = 0; j < 8; j++) acc4w(acc, w[j], r[j]);
    }
    for (; p < end; ++p) {
        int s = g_csrc[p];
        acc4w(acc, g_dis[s], *(const uint2*)(g_h1 + (size_t)s * CH + lane * 4));
    }
    float di = g_dis[node];
    acc4w(acc, di, *(const uint2*)(g_h1 + (size_t)node * CH + lane * 4));
    float4 b = ((const float4*)b1)[lane];
    float o0 = fmaxf(fmaf(di, acc[0], b.x), 0.f);
    float o1 = fmaxf(fmaf(di, acc[1], b.y), 0.f);
    float o2 = fmaxf(fmaf(di, acc[2], b.z), 0.f);
    float o3 = fmaxf(fmaf(di, acc[3], b.w), 0.f);
    uint2 outw;
    *(__half2*)&outw.x = __floats2half2_rn(o0, o1);
    *(__half2*)&outw.y = __floats2half2_rn(o2, o3);
    *(uint2*)(g_h + (size_t)node * CH + lane * 4) = outw;
}

// Layer-2 aggregation (h2s pre-scaled, fp16), fused self-loop+bias; fp32 out.
__global__ void k_aggB(const float* __restrict__ b2, float* __restrict__ out, int n) {
    int g = blockIdx.x * blockDim.x + threadIdx.x;
    int node = g / 10, l = g % 10;
    if (node >= n) return;
    int end = g_incl[node];
    int p = end - g_cnt[node];
    float acc[4] = {0.f, 0.f, 0.f, 0.f};
    for (; p + 4 <= end; p += 4) {
        int s0 = g_csrc[p], s1 = g_csrc[p + 1], s2 = g_csrc[p + 2], s3 = g_csrc[p + 3];
        uint2 r0 = *(const uint2*)(g_h2s + (size_t)s0 * COUT + l * 4);
        uint2 r1 = *(const uint2*)(g_h2s + (size_t)s1 * COUT + l * 4);
        uint2 r2 = *(const uint2*)(g_h2s + (size_t)s2 * COUT + l * 4);
        uint2 r3 = *(const uint2*)(g_h2s + (size_t)s3 * COUT + l * 4);
        acc4(acc, r0); acc4(acc, r1); acc4(acc, r2); acc4(acc, r3);
    }
    for (; p < end; ++p) {
        int s = g_csrc[p];
        acc4(acc, *(const uint2*)(g_h2s + (size_t)s * COUT + l * 4));
    }
    acc4(acc, *(const uint2*)(g_h2s + (size_t)node * COUT + l * 4));
    float di = g_dis[node];
    float4 b = *(const float4*)(b2 + l * 4);
    float4 r;
    r.x = fmaf(di, acc[0], b.x);
    r.y = fmaf(di, acc[1], b.y);
    r.z = fmaf(di, acc[2], b.z);
    r.w = fmaf(di, acc[3], b.w);
    *(float4*)(out + (size_t)node * COUT + l * 4) = r;
}

// ---------------------------------------------------------------------------
extern "C" void kernel_launch(void* const* d_in, const int* in_sizes, int n_in,
                              void* d_out, int out_size) {
    const float* x  = (const float*)d_in[0];
    const float* W1 = (const float*)d_in[1];
    const float* b1 = (const float*)d_in[2];
    const float* W2 = (const float*)d_in[3];
    const float* b2 = (const float*)d_in[4];
    const int* edge = (const int*)d_in[5];

    const int n = in_sizes[0] / CIN;
    const int e = in_sizes[5] / 2;
    const int* src = edge;
    const int* dst = edge + e;
    float* out = (float*)d_out;

    __half *p_h1 = nullptr, *p_h = nullptr, *p_h2s = nullptr;
    __half *p_w1h = nullptr, *p_w2h = nullptr;
    cudaGetSymbolAddress((void**)&p_h1, g_h1);
    cudaGetSymbolAddress((void**)&p_h, g_h);
    cudaGetSymbolAddress((void**)&p_h2s, g_h2s);
    cudaGetSymbolAddress((void**)&p_w1h, g_w1h);
    cudaGetSymbolAddress((void**)&p_w2h, g_w2h);

    const int smem1 = (64 * KS + 128 * KS) * 2;  // 52224 B -> 4 CTAs/SM
    const int smem2 = (64 * KS + 64 * KS) * 2;   // 34816 B -> 6 CTAs/SM
    cudaFuncSetAttribute(k_mma<128, false, float>, cudaFuncAttributeMaxDynamicSharedMemorySize, smem1);
    cudaFuncSetAttribute(k_mma<64, true, __half>,  cudaFuncAttributeMaxDynamicSharedMemorySize, smem2);

    static cudaStream_t s1 = nullptr, s2 = nullptr;
    static cudaEvent_t evFork = nullptr, evJoin = nullptr, evDone = nullptr;
    if (s1 == nullptr) {
        cudaStreamCreateWithFlags(&s1, cudaStreamNonBlocking);
        cudaStreamCreateWithFlags(&s2, cudaStreamNonBlocking);
        cudaEventCreateWithFlags(&evFork, cudaEventDisableTiming);
        cudaEventCreateWithFlags(&evJoin, cudaEventDisableTiming);
        cudaEventCreateWithFlags(&evDone, cudaEventDisableTiming);
    }

    // Fork into s1 (GEMM chain) and s2 (CSR).
    cudaEventRecord(evFork, 0);
    cudaStreamWaitEvent(s1, evFork, 0);
    cudaStreamWaitEvent(s2, evFork, 0);

    // CSR branch (latency-bound; overlaps with GEMM1)
    k_zero<<<(n + 255) / 256, 256, 0, s2>>>(n);
    k_hist<<<(e + 255) / 256, 256, 0, s2>>>(dst, e);
    k_scanDL<<<NBLK, SCAN_B, 0, s2>>>(n);
    k_scatter<<<(e + 255) / 256, 256, 0, s2>>>(src, dst, e);
    cudaEventRecord(evJoin, s2);

    // GEMM branch: W pre-convert, then GEMM1
    k_wconv<<<(128 * 128 + 64 * 128 + 255) / 256, 256, 0, s1>>>(W1, W2);
    k_mma<128, false, float><<<(n + 63) / 64, 256, smem1, s1>>>(x, p_w1h, 128, p_h1, n);

    // Join: aggregation needs CSR + dis + h1
    cudaStreamWaitEvent(s1, evJoin, 0);
    k_aggA<<<(int)(((size_t)n * 32 + 255) / 256), 256, 0, s1>>>(b1, n);

    // layer 2 (GEMM first: aggregate only 40 channels)
    k_mma<64, true, __half><<<(n + 63) / 64, 256, smem2, s1>>>(p_h, p_w2h, COUT, p_h2s, n);
    k_aggB<<<(int)(((size_t)n * 10 + 319) / 320), 320, 0, s1>>>(b2, out, n);

    // Join back to the launch stream.
    cudaEventRecord(evDone, s1);
    cudaStreamWaitEvent(0, evDone, 0);
}

// round 14
// speedup vs baseline: 1.7649x; 1.0546x over previous
#include <cuda_runtime.h>
#include <cuda_bf16.h>
#include <cuda_fp16.h>
#include <cstdint>

// Problem constants (N=170000, E=1200000, IN=HID=128, OUT=40)
#define NN 170000
#define EE 1200000
#define CIN 128
#define CH 128
#define COUT 40
#define SCAN_B 512
#define NBLK ((NN + SCAN_B - 1) / SCAN_B)   // 333
#define KS 136   // smem k-stride (halves), padded for conflict-free LDSM

// Scratch (static __device__ arrays per allocation rules)
__device__ __half g_h1[(size_t)NN * CH];     // x @ W1 (UNscaled), fp16
__device__ __half g_h[(size_t)NN * CH];      // relu'd hidden, fp16
__device__ __half g_h2s[(size_t)NN * COUT];  // dis * (h @ W2), fp16
__device__ __align__(16) __half g_w1h[128 * KS];  // W1^T fp16, padded rows
__device__ __align__(16) __half g_w2h[64 * KS];   // W2^T fp16 (zero-pad cols>=40)
__device__ float g_dis[NN];
__device__ int g_cnt[NN];
__device__ int g_incl[NN];
__device__ int g_start[NN];   // scatter cursor (destroyed by k_scatter)
__device__ volatile int g_flag[NBLK];
__device__ volatile int g_aggv[NBLK];
__device__ volatile int g_pref[NBLK];
__device__ int g_csrc[EE];   // edge srcs grouped by dst

// ---------------------------------------------------------------------------
__global__ void k_zero(int n) {
    int i = blockIdx.x * blockDim.x + threadIdx.x;
    if (i < n) g_cnt[i] = 0;
    if (i < NBLK) g_flag[i] = 0;
}

__global__ void k_hist(const int* __restrict__ dst, int e) {
    int i = blockIdx.x * blockDim.x + threadIdx.x;
    if (i < e) atomicAdd(&g_cnt[dst[i]], 1);
}

// W1/W2 -> transposed fp16 buffers in the exact smem layout (n-major, KS stride)
__global__ void k_wconv(const float* __restrict__ W1, const float* __restrict__ W2) {
    int i = blockIdx.x * blockDim.x + threadIdx.x;
    if (i < 128 * 128) {
        int nn = i >> 7, k = i & 127;
        g_w1h[nn * KS + k] = __float2half(W1[k * 128 + nn]);
    } else if (i < 128 * 128 + 64 * 128) {
        int j = i - 128 * 128;
        int nn = j >> 7, k = j & 127;
        float v = (nn < COUT) ? W2[k * COUT + nn] : 0.f;
        g_w2h[nn * KS + k] = __float2half(v);
    }
}

// Single-pass inclusive scan of g_cnt (decoupled lookback) + fused dis/start.
__global__ void k_scanDL(int n) {
    __shared__ int sm[SCAN_B];
    __shared__ int s_excl;
    const int t = threadIdx.x, bid = blockIdx.x;
    const int i = bid * SCAN_B + t;
    int v = (i < n) ? g_cnt[i] : 0;
    sm[t] = v;
    __syncthreads();
#pragma unroll
    for (int off = 1; off < SCAN_B; off <<= 1) {
        int u = (t >= off) ? sm[t - off] : 0;
        __syncthreads();
        sm[t] += u;
        __syncthreads();
    }
    const int incl_local = sm[t];
    const int agg = sm[SCAN_B - 1];

    if (bid == 0) {
        if (t == 0) {
            g_pref[0] = agg;
            __threadfence();
            g_flag[0] = 2;
            s_excl = 0;
        }
    } else {
        if (t == 0) {
            g_aggv[bid] = agg;
            __threadfence();
            g_flag[bid] = 1;
        }
        if (t < 32) {
            int excl = 0;
            for (int base = bid - 1; base >= 0; base -= 32) {
                int j = base - t;
                int f = 0, a = 0;
                if (j >= 0) {
                    while ((f = g_flag[j]) == 0) {}
                    a = (f == 2) ? g_pref[j] : g_aggv[j];
                }
                unsigned done = __ballot_sync(0xffffffffu, (j >= 0) && (f == 2));
                int contrib;
                if (done) {
                    int firstLane = __ffs(done) - 1;
                    contrib = (t <= firstLane) ? a : 0;
                } else {
                    contrib = (j >= 0) ? a : 0;
                }
#pragma unroll
                for (int o = 16; o; o >>= 1) contrib += __shfl_xor_sync(0xffffffffu, contrib, o);
                excl += contrib;
                if (done) break;
            }
            if (t == 0) {
                g_pref[bid] = excl + agg;
                __threadfence();
                g_flag[bid] = 2;
                s_excl = excl;
            }
        }
    }
    __syncthreads();
    const int excl = s_excl;
    if (i < n) {
        int incl = incl_local + excl;
        g_incl[i] = incl;
        g_start[i] = incl - v;   // also serves as scatter cursor
        g_dis[i] = rsqrtf((float)(v + 1));  // +1 self-loop
    }
}

// scatter using g_start as the cursor (destroys it; aggA recomputes start)
__global__ void k_scatter(const int* __restrict__ src, const int* __restrict__ dst, int e) {
    int i = blockIdx.x * blockDim.x + threadIdx.x;
    if (i >= e) return;
    int d = dst[i];
    int pos = atomicAdd(&g_start[d], 1);
    g_csrc[pos] = src[i];
}

// ---------------------------------------------------------------------------
// fp16 single-pass tensor-core GEMM:
//   Y(fp16) = (optionally dis[row] *) X[row,:128] @ W[:128, wcols]
__device__ __forceinline__ void ldsm_x4(uint32_t* r, uint32_t addr) {
    asm volatile("ldmatrix.sync.aligned.m8n8.x4.shared.b16 {%0,%1,%2,%3}, [%4];"
                 : "=r"(r[0]), "=r"(r[1]), "=r"(r[2]), "=r"(r[3]) : "r"(addr));
}
__device__ __forceinline__ void ldsm_x2(uint32_t* r, uint32_t addr) {
    asm volatile("ldmatrix.sync.aligned.m8n8.x2.shared.b16 {%0,%1}, [%2];"
                 : "=r"(r[0]), "=r"(r[1]) : "r"(addr));
}
__device__ __forceinline__ void mma_f16(float* d, const uint32_t* a, const uint32_t* b) {
    asm volatile("mma.sync.aligned.m16n8k16.row.col.f32.f16.f16.f32 "
                 "{%0,%1,%2,%3}, {%4,%5,%6,%7}, {%8,%9}, {%0,%1,%2,%3};"
                 : "+f"(d[0]), "+f"(d[1]), "+f"(d[2]), "+f"(d[3])
                 : "r"(a[0]), "r"(a[1]), "r"(a[2]), "r"(a[3]), "r"(b[0]), "r"(b[1]));
}

template <int CO, bool SCALE, typename TIN>
__global__ void __launch_bounds__(256, (CO == 128) ? 4 : 6)
k_mma(const TIN* __restrict__ X, const __half* __restrict__ Wh, int wcols,
      __half* __restrict__ Y, int n) {
    extern __shared__ char smc[];
    __half* Ah = (__half*)smc;           // 64*KS
    __half* Ws = Ah + 64 * KS;           // CO*KS

    const int t = threadIdx.x;
    const int row0 = blockIdx.x * 64;

    for (int idx = t; idx < CO * 17; idx += 256)
        ((uint4*)Ws)[idx] = ((const uint4*)Wh)[idx];

    if (sizeof(TIN) == 4) {
        for (int idx = t; idx < 64 * 32; idx += 256) {
            int r = idx >> 5, c4 = idx & 31;
            float4 v = make_float4(0.f, 0.f, 0.f, 0.f);
            if (row0 + r < n)
                v = ((const float4*)((const float*)X + (size_t)(row0 + r) * 128))[c4];
            __half2 p0 = __floats2half2_rn(v.x, v.y);
            __half2 p1 = __floats2half2_rn(v.z, v.w);
            uint2 w;
            w.x = *(uint32_t*)&p0;
            w.y = *(uint32_t*)&p1;
            *(uint2*)(Ah + r * KS + c4 * 4) = w;
        }
    } else {
        for (int idx = t; idx < 64 * 16; idx += 256) {
            int r = idx >> 4, c8 = idx & 15;
            uint4 v = make_uint4(0, 0, 0, 0);
            if (row0 + r < n)
                v = *(const uint4*)((const __half*)X + (size_t)(row0 + r) * 128 + c8 * 8);
            *(uint4*)(Ah + r * KS + c8 * 8) = v;
        }
    }
    __syncthreads();

    const int w = t >> 5, lane = t & 31;
    const int wm = w & 1, wn = w >> 1;          // 2(M) x 4(N)
    constexpr int NF = CO / 32;
    constexpr int WN = CO / 4;

    uint32_t sbase;
    asm("{ .reg .u64 tt; cvta.to.shared.u64 tt, %1; cvt.u32.u64 %0, tt; }"
        : "=r"(sbase) : "l"(smc));
    const uint32_t aB = sbase;
    const uint32_t wB = sbase + 64 * KS * 2;

    uint32_t aOff[2];
#pragma unroll
    for (int mf = 0; mf < 2; mf++) {
        int row = wm * 32 + mf * 16 + (lane & 15);
        aOff[mf] = (uint32_t)(row * KS + ((lane >> 4) << 3)) * 2;
    }
    uint32_t bOff[NF];
#pragma unroll
    for (int nf = 0; nf < NF; nf++) {
        int nr = wn * WN + nf * 8 + (lane & 7);
        bOff[nf] = (uint32_t)(nr * KS + (lane & 8)) * 2;
    }

    float acc[2][NF][4];
#pragma unroll
    for (int mf = 0; mf < 2; mf++)
#pragma unroll
        for (int nf = 0; nf < NF; nf++)
#pragma unroll
            for (int i = 0; i < 4; i++) acc[mf][nf][i] = 0.f;

#pragma unroll
    for (int ks = 0; ks < 8; ks++) {
        const uint32_t kb = ks * 16 * 2;
        uint32_t ah[2][4], bh[NF][2];
#pragma unroll
        for (int mf = 0; mf < 2; mf++) ldsm_x4(ah[mf], aB + aOff[mf] + kb);
#pragma unroll
        for (int nf = 0; nf < NF; nf++) ldsm_x2(bh[nf], wB + bOff[nf] + kb);
#pragma unroll
        for (int mf = 0; mf < 2; mf++)
#pragma unroll
            for (int nf = 0; nf < NF; nf++)
                mma_f16(acc[mf][nf], ah[mf], bh[nf]);
    }

#pragma unroll
    for (int mf = 0; mf < 2; mf++) {
        int rowA = row0 + wm * 32 + mf * 16 + (lane >> 2);
        int rowB = rowA + 8;
        float dA = 1.f, dB = 1.f;
        if (SCALE) {
            dA = (rowA < n) ? g_dis[rowA] : 0.f;
            dB = (rowB < n) ? g_dis[rowB] : 0.f;
        }
#pragma unroll
        for (int nf = 0; nf < NF; nf++) {
            int col = wn * WN + nf * 8 + ((lane & 3) << 1);
            if (CO != 128 && col >= wcols) continue;
            if (rowA < n) {
                __half2 v = __floats2half2_rn(acc[mf][nf][0] * dA, acc[mf][nf][1] * dA);
                *(__half2*)(Y + (size_t)rowA * wcols + col) = v;
            }
            if (rowB < n) {
                __half2 v = __floats2half2_rn(acc[mf][nf][2] * dB, acc[mf][nf][3] * dB);
                *(__half2*)(Y + (size_t)rowB * wcols + col) = v;
            }
        }
    }
}

// ---------------------------------------------------------------------------
// fp16 8-channel accumulate: acc += w * v (v = 8 halves in uint4)
__device__ __forceinline__ void acc8w(float* acc, float w, uint4 r) {
    float2 f0 = __half22float2(*(__half2*)&r.x);
    float2 f1 = __half22float2(*(__half2*)&r.y);
    float2 f2 = __half22float2(*(__half2*)&r.z);
    float2 f3 = __half22float2(*(__half2*)&r.w);
    acc[0] = fmaf(w, f0.x, acc[0]); acc[1] = fmaf(w, f0.y, acc[1]);
    acc[2] = fmaf(w, f1.x, acc[2]); acc[3] = fmaf(w, f1.y, acc[3]);
    acc[4] = fmaf(w, f2.x, acc[4]); acc[5] = fmaf(w, f2.y, acc[5]);
    acc[6] = fmaf(w, f3.x, acc[6]); acc[7] = fmaf(w, f3.y, acc[7]);
}
__device__ __forceinline__ void acc4(float* acc, uint2 raw) {
    float2 f0 = __half22float2(*(__half2*)&raw.x);
    float2 f1 = __half22float2(*(__half2*)&raw.y);
    acc[0] += f0.x; acc[1] += f0.y; acc[2] += f1.x; acc[3] += f1.y;
}

// Layer-1 aggregation: TWO nodes per warp, each owned by a 16-lane half-warp
// (uint4 = 8 ch/lane, 128 ch total). No cross-half shuffle. Unroll 4.
__global__ void k_aggA(const float* __restrict__ b1, int n) {
    int g = blockIdx.x * blockDim.x + threadIdx.x;
    int hw = g >> 4;           // half-warp index = node
    int node = hw;
    int l = g & 15;            // lane within half-warp
    if (node >= n) return;
    const size_t chOff = (size_t)l * 8;
    int end = g_incl[node];
    int p = end - g_cnt[node];
    float acc[8] = {0.f, 0.f, 0.f, 0.f, 0.f, 0.f, 0.f, 0.f};
    for (; p + 4 <= end; p += 4) {
        int s0 = g_csrc[p], s1 = g_csrc[p + 1], s2 = g_csrc[p + 2], s3 = g_csrc[p + 3];
        float w0 = g_dis[s0], w1 = g_dis[s1], w2 = g_dis[s2], w3 = g_dis[s3];
        uint4 r0 = *(const uint4*)(g_h1 + (size_t)s0 * CH + chOff);
        uint4 r1 = *(const uint4*)(g_h1 + (size_t)s1 * CH + chOff);
        uint4 r2 = *(const uint4*)(g_h1 + (size_t)s2 * CH + chOff);
        uint4 r3 = *(const uint4*)(g_h1 + (size_t)s3 * CH + chOff);
        acc8w(acc, w0, r0); acc8w(acc, w1, r1); acc8w(acc, w2, r2); acc8w(acc, w3, r3);
    }
    for (; p < end; ++p) {
        int s = g_csrc[p];
        acc8w(acc, g_dis[s], *(const uint4*)(g_h1 + (size_t)s * CH + chOff));
    }
    float di = g_dis[node];
    acc8w(acc, di, *(const uint4*)(g_h1 + (size_t)node * CH + chOff));
    float4 ba = ((const float4*)b1)[l * 2];
    float4 bb = ((const float4*)b1)[l * 2 + 1];
    float o0 = fmaxf(fmaf(di, acc[0], ba.x), 0.f);
    float o1 = fmaxf(fmaf(di, acc[1], ba.y), 0.f);
    float o2 = fmaxf(fmaf(di, acc[2], ba.z), 0.f);
    float o3 = fmaxf(fmaf(di, acc[3], ba.w), 0.f);
    float o4 = fmaxf(fmaf(di, acc[4], bb.x), 0.f);
    float o5 = fmaxf(fmaf(di, acc[5], bb.y), 0.f);
    float o6 = fmaxf(fmaf(di, acc[6], bb.z), 0.f);
    float o7 = fmaxf(fmaf(di, acc[7], bb.w), 0.f);
    uint4 w;
    *(__half2*)&w.x = __floats2half2_rn(o0, o1);
    *(__half2*)&w.y = __floats2half2_rn(o2, o3);
    *(__half2*)&w.z = __floats2half2_rn(o4, o5);
    *(__half2*)&w.w = __floats2half2_rn(o6, o7);
    *(uint4*)(g_h + (size_t)node * CH + chOff) = w;
}

// Layer-2 aggregation (h2s pre-scaled, fp16), fused self-loop+bias; fp32 out.
__global__ void k_aggB(const float* __restrict__ b2, float* __restrict__ out, int n) {
    int g = blockIdx.x * blockDim.x + threadIdx.x;
    int node = g / 10, l = g % 10;
    if (node >= n) return;
    int end = g_incl[node];
    int p = end - g_cnt[node];
    float acc[4] = {0.f, 0.f, 0.f, 0.f};
    for (; p + 4 <= end; p += 4) {
        int s0 = g_csrc[p], s1 = g_csrc[p + 1], s2 = g_csrc[p + 2], s3 = g_csrc[p + 3];
        uint2 r0 = *(const uint2*)(g_h2s + (size_t)s0 * COUT + l * 4);
        uint2 r1 = *(const uint2*)(g_h2s + (size_t)s1 * COUT + l * 4);
        uint2 r2 = *(const uint2*)(g_h2s + (size_t)s2 * COUT + l * 4);
        uint2 r3 = *(const uint2*)(g_h2s + (size_t)s3 * COUT + l * 4);
        acc4(acc, r0); acc4(acc, r1); acc4(acc, r2); acc4(acc, r3);
    }
    for (; p < end; ++p) {
        int s = g_csrc[p];
        acc4(acc, *(const uint2*)(g_h2s + (size_t)s * COUT + l * 4));
    }
    acc4(acc, *(const uint2*)(g_h2s + (size_t)node * COUT + l * 4));
    float di = g_dis[node];
    float4 b = *(const float4*)(b2 + l * 4);
    float4 r;
    r.x = fmaf(di, acc[0], b.x);
    r.y = fmaf(di, acc[1], b.y);
    r.z = fmaf(di, acc[2], b.z);
    r.w = fmaf(di, acc[3], b.w);
    *(float4*)(out + (size_t)node * COUT + l * 4) = r;
}

// ---------------------------------------------------------------------------
extern "C" void kernel_launch(void* const* d_in, const int* in_sizes, int n_in,
                              void* d_out, int out_size) {
    const float* x  = (const float*)d_in[0];
    const float* W1 = (const float*)d_in[1];
    const float* b1 = (const float*)d_in[2];
    const float* W2 = (const float*)d_in[3];
    const float* b2 = (const float*)d_in[4];
    const int* edge = (const int*)d_in[5];

    const int n = in_sizes[0] / CIN;
    const int e = in_sizes[5] / 2;
    const int* src = edge;
    const int* dst = edge + e;
    float* out = (float*)d_out;

    __half *p_h1 = nullptr, *p_h = nullptr, *p_h2s = nullptr;
    __half *p_w1h = nullptr, *p_w2h = nullptr;
    cudaGetSymbolAddress((void**)&p_h1, g_h1);
    cudaGetSymbolAddress((void**)&p_h, g_h);
    cudaGetSymbolAddress((void**)&p_h2s, g_h2s);
    cudaGetSymbolAddress((void**)&p_w1h, g_w1h);
    cudaGetSymbolAddress((void**)&p_w2h, g_w2h);

    const int smem1 = (64 * KS + 128 * KS) * 2;  // 52224 B -> 4 CTAs/SM
    const int smem2 = (64 * KS + 64 * KS) * 2;   // 34816 B -> 6 CTAs/SM
    cudaFuncSetAttribute(k_mma<128, false, float>, cudaFuncAttributeMaxDynamicSharedMemorySize, smem1);
    cudaFuncSetAttribute(k_mma<64, true, __half>,  cudaFuncAttributeMaxDynamicSharedMemorySize, smem2);

    static cudaStream_t s1 = nullptr, s2 = nullptr;
    static cudaEvent_t evFork = nullptr, evJoin = nullptr, evDone = nullptr;
    if (s1 == nullptr) {
        cudaStreamCreateWithFlags(&s1, cudaStreamNonBlocking);
        cudaStreamCreateWithFlags(&s2, cudaStreamNonBlocking);
        cudaEventCreateWithFlags(&evFork, cudaEventDisableTiming);
        cudaEventCreateWithFlags(&evJoin, cudaEventDisableTiming);
        cudaEventCreateWithFlags(&evDone, cudaEventDisableTiming);
    }

    // Fork into s1 (GEMM chain) and s2 (CSR).
    cudaEventRecord(evFork, 0);
    cudaStreamWaitEvent(s1, evFork, 0);
    cudaStreamWaitEvent(s2, evFork, 0);

    // CSR branch (latency-bound; overlaps with GEMM1)
    k_zero<<<(n + 255) / 256, 256, 0, s2>>>(n);
    k_hist<<<(e + 255) / 256, 256, 0, s2>>>(dst, e);
    k_scanDL<<<NBLK, SCAN_B, 0, s2>>>(n);
    k_scatter<<<(e + 255) / 256, 256, 0, s2>>>(src, dst, e);
    cudaEventRecord(evJoin, s2);

    // GEMM branch: W pre-convert, then GEMM1
    k_wconv<<<(128 * 128 + 64 * 128 + 255) / 256, 256, 0, s1>>>(W1, W2);
    k_mma<128, false, float><<<(n + 63) / 64, 256, smem1, s1>>>(x, p_w1h, 128, p_h1, n);

    // Join: aggregation needs CSR + dis + h1
    cudaStreamWaitEvent(s1, evJoin, 0);
    k_aggA<<<(int)(((size_t)n * 16 + 255) / 256), 256, 0, s1>>>(b1, n);

    // layer 2 (GEMM first: aggregate only 40 channels)
    k_mma<64, true, __half><<<(n + 63) / 64, 256, smem2, s1>>>(p_h, p_w2h, COUT, p_h2s, n);
    k_aggB<<<(int)(((size_t)n * 10 + 319) / 320), 320, 0, s1>>>(b2, out, n);

    // Join back to the launch stream.
    cudaEventRecord(evDone, s1);
    cudaStreamWaitEvent(0, evDone, 0);
}

// round 15
// speedup vs baseline: 1.7710x; 1.0034x over previous
#include <cuda_runtime.h>
#include <cuda_bf16.h>
#include <cuda_fp16.h>
#include <cstdint>

// Problem constants (N=170000, E=1200000, IN=HID=128, OUT=40)
#define NN 170000
#define EE 1200000
#define CIN 128
#define CH 128
#define COUT 40
#define SCAN_B 512
#define NBLK ((NN + SCAN_B - 1) / SCAN_B)   // 333
#define KS 136   // smem k-stride (halves), padded for conflict-free LDSM

// Scratch (static __device__ arrays per allocation rules)
__device__ __half g_h1[(size_t)NN * CH];     // x @ W1 (UNscaled), fp16
__device__ __half g_h[(size_t)NN * CH];      // relu'd hidden, fp16
__device__ __half g_h2s[(size_t)NN * COUT];  // dis * (h @ W2), fp16
__device__ __align__(16) __half g_w1h[128 * KS];  // W1^T fp16, padded rows
__device__ __align__(16) __half g_w2h[64 * KS];   // W2^T fp16 (zero-pad cols>=40)
__device__ float g_dis[NN];
__device__ int g_cnt[NN];
__device__ int g_incl[NN];
__device__ int g_start[NN];   // scatter cursor (destroyed by k_scatter)
__device__ volatile int g_flag[NBLK];
__device__ volatile int g_aggv[NBLK];
__device__ volatile int g_pref[NBLK];
__device__ int g_csrc[EE];   // edge srcs grouped by dst

// ---------------------------------------------------------------------------
__global__ void k_hist(const int* __restrict__ dst, int e) {
    int i = blockIdx.x * blockDim.x + threadIdx.x;
    if (i < e) atomicAdd(&g_cnt[dst[i]], 1);
}

// W1/W2 -> transposed fp16 buffers in the exact smem layout (n-major, KS stride)
__global__ void k_wconv(const float* __restrict__ W1, const float* __restrict__ W2) {
    int i = blockIdx.x * blockDim.x + threadIdx.x;
    if (i < 128 * 128) {
        int nn = i >> 7, k = i & 127;
        g_w1h[nn * KS + k] = __float2half(W1[k * 128 + nn]);
    } else if (i < 128 * 128 + 64 * 128) {
        int j = i - 128 * 128;
        int nn = j >> 7, k = j & 127;
        float v = (nn < COUT) ? W2[k * COUT + nn] : 0.f;
        g_w2h[nn * KS + k] = __float2half(v);
    }
}

// Single-pass inclusive scan of g_cnt (decoupled lookback) + fused dis/start.
__global__ void k_scanDL(int n) {
    __shared__ int sm[SCAN_B];
    __shared__ int s_excl;
    const int t = threadIdx.x, bid = blockIdx.x;
    const int i = bid * SCAN_B + t;
    int v = (i < n) ? g_cnt[i] : 0;
    sm[t] = v;
    __syncthreads();
#pragma unroll
    for (int off = 1; off < SCAN_B; off <<= 1) {
        int u = (t >= off) ? sm[t - off] : 0;
        __syncthreads();
        sm[t] += u;
        __syncthreads();
    }
    const int incl_local = sm[t];
    const int agg = sm[SCAN_B - 1];

    if (bid == 0) {
        if (t == 0) {
            g_pref[0] = agg;
            __threadfence();
            g_flag[0] = 2;
            s_excl = 0;
        }
    } else {
        if (t == 0) {
            g_aggv[bid] = agg;
            __threadfence();
            g_flag[bid] = 1;
        }
        if (t < 32) {
            int excl = 0;
            for (int base = bid - 1; base >= 0; base -= 32) {
                int j = base - t;
                int f = 0, a = 0;
                if (j >= 0) {
                    while ((f = g_flag[j]) == 0) {}
                    a = (f == 2) ? g_pref[j] : g_aggv[j];
                }
                unsigned done = __ballot_sync(0xffffffffu, (j >= 0) && (f == 2));
                int contrib;
                if (done) {
                    int firstLane = __ffs(done) - 1;
                    contrib = (t <= firstLane) ? a : 0;
                } else {
                    contrib = (j >= 0) ? a : 0;
                }
#pragma unroll
                for (int o = 16; o; o >>= 1) contrib += __shfl_xor_sync(0xffffffffu, contrib, o);
                excl += contrib;
                if (done) break;
            }
            if (t == 0) {
                g_pref[bid] = excl + agg;
                __threadfence();
                g_flag[bid] = 2;
                s_excl = excl;
            }
        }
    }
    __syncthreads();
    const int excl = s_excl;
    if (i < n) {
        int incl = incl_local + excl;
        g_incl[i] = incl;
        g_start[i] = incl - v;   // also serves as scatter cursor
        g_dis[i] = rsqrtf((float)(v + 1));  // +1 self-loop
    }
}

// scatter using g_start as the cursor (destroys it; agg kernels recompute start)
__global__ void k_scatter(const int* __restrict__ src, const int* __restrict__ dst, int e) {
    int i = blockIdx.x * blockDim.x + threadIdx.x;
    if (i >= e) return;
    int d = dst[i];
    int pos = atomicAdd(&g_start[d], 1);
    g_csrc[pos] = src[i];
}

// ---------------------------------------------------------------------------
// fp16 single-pass tensor-core GEMM:
//   Y(fp16) = (optionally dis[row] *) X[row,:128] @ W[:128, wcols]
__device__ __forceinline__ void ldsm_x4(uint32_t* r, uint32_t addr) {
    asm volatile("ldmatrix.sync.aligned.m8n8.x4.shared.b16 {%0,%1,%2,%3}, [%4];"
                 : "=r"(r[0]), "=r"(r[1]), "=r"(r[2]), "=r"(r[3]) : "r"(addr));
}
__device__ __forceinline__ void ldsm_x2(uint32_t* r, uint32_t addr) {
    asm volatile("ldmatrix.sync.aligned.m8n8.x2.shared.b16 {%0,%1}, [%2];"
                 : "=r"(r[0]), "=r"(r[1]) : "r"(addr));
}
__device__ __forceinline__ void mma_f16(float* d, const uint32_t* a, const uint32_t* b) {
    asm volatile("mma.sync.aligned.m16n8k16.row.col.f32.f16.f16.f32 "
                 "{%0,%1,%2,%3}, {%4,%5,%6,%7}, {%8,%9}, {%0,%1,%2,%3};"
                 : "+f"(d[0]), "+f"(d[1]), "+f"(d[2]), "+f"(d[3])
                 : "r"(a[0]), "r"(a[1]), "r"(a[2]), "r"(a[3]), "r"(b[0]), "r"(b[1]));
}

template <int CO, bool SCALE, typename TIN>
__global__ void __launch_bounds__(256, (CO == 128) ? 4 : 6)
k_mma(const TIN* __restrict__ X, const __half* __restrict__ Wh, int wcols,
      __half* __restrict__ Y, int n) {
    extern __shared__ char smc[];
    __half* Ah = (__half*)smc;           // 64*KS
    __half* Ws = Ah + 64 * KS;           // CO*KS

    const int t = threadIdx.x;
    const int row0 = blockIdx.x * 64;

    for (int idx = t; idx < CO * 17; idx += 256)
        ((uint4*)Ws)[idx] = ((const uint4*)Wh)[idx];

    if (sizeof(TIN) == 4) {
        for (int idx = t; idx < 64 * 32; idx += 256) {
            int r = idx >> 5, c4 = idx & 31;
            float4 v = make_float4(0.f, 0.f, 0.f, 0.f);
            if (row0 + r < n)
                v = ((const float4*)((const float*)X + (size_t)(row0 + r) * 128))[c4];
            __half2 p0 = __floats2half2_rn(v.x, v.y);
            __half2 p1 = __floats2half2_rn(v.z, v.w);
            uint2 w;
            w.x = *(uint32_t*)&p0;
            w.y = *(uint32_t*)&p1;
            *(uint2*)(Ah + r * KS + c4 * 4) = w;
        }
    } else {
        for (int idx = t; idx < 64 * 16; idx += 256) {
            int r = idx >> 4, c8 = idx & 15;
            uint4 v = make_uint4(0, 0, 0, 0);
            if (row0 + r < n)
                v = *(const uint4*)((const __half*)X + (size_t)(row0 + r) * 128 + c8 * 8);
            *(uint4*)(Ah + r * KS + c8 * 8) = v;
        }
    }
    __syncthreads();

    const int w = t >> 5, lane = t & 31;
    const int wm = w & 1, wn = w >> 1;          // 2(M) x 4(N)
    constexpr int NF = CO / 32;
    constexpr int WN = CO / 4;

    uint32_t sbase;
    asm("{ .reg .u64 tt; cvta.to.shared.u64 tt, %1; cvt.u32.u64 %0, tt; }"
        : "=r"(sbase) : "l"(smc));
    const uint32_t aB = sbase;
    const uint32_t wB = sbase + 64 * KS * 2;

    uint32_t aOff[2];
#pragma unroll
    for (int mf = 0; mf < 2; mf++) {
        int row = wm * 32 + mf * 16 + (lane & 15);
        aOff[mf] = (uint32_t)(row * KS + ((lane >> 4) << 3)) * 2;
    }
    uint32_t bOff[NF];
#pragma unroll
    for (int nf = 0; nf < NF; nf++) {
        int nr = wn * WN + nf * 8 + (lane & 7);
        bOff[nf] = (uint32_t)(nr * KS + (lane & 8)) * 2;
    }

    float acc[2][NF][4];
#pragma unroll
    for (int mf = 0; mf < 2; mf++)
#pragma unroll
        for (int nf = 0; nf < NF; nf++)
#pragma unroll
            for (int i = 0; i < 4; i++) acc[mf][nf][i] = 0.f;

#pragma unroll
    for (int ks = 0; ks < 8; ks++) {
        const uint32_t kb = ks * 16 * 2;
        uint32_t ah[2][4], bh[NF][2];
#pragma unroll
        for (int mf = 0; mf < 2; mf++) ldsm_x4(ah[mf], aB + aOff[mf] + kb);
#pragma unroll
        for (int nf = 0; nf < NF; nf++) ldsm_x2(bh[nf], wB + bOff[nf] + kb);
#pragma unroll
        for (int mf = 0; mf < 2; mf++)
#pragma unroll
            for (int nf = 0; nf < NF; nf++)
                mma_f16(acc[mf][nf], ah[mf], bh[nf]);
    }

#pragma unroll
    for (int mf = 0; mf < 2; mf++) {
        int rowA = row0 + wm * 32 + mf * 16 + (lane >> 2);
        int rowB = rowA + 8;
        float dA = 1.f, dB = 1.f;
        if (SCALE) {
            dA = (rowA < n) ? g_dis[rowA] : 0.f;
            dB = (rowB < n) ? g_dis[rowB] : 0.f;
        }
#pragma unroll
        for (int nf = 0; nf < NF; nf++) {
            int col = wn * WN + nf * 8 + ((lane & 3) << 1);
            if (CO != 128 && col >= wcols) continue;
            if (rowA < n) {
                __half2 v = __floats2half2_rn(acc[mf][nf][0] * dA, acc[mf][nf][1] * dA);
                *(__half2*)(Y + (size_t)rowA * wcols + col) = v;
            }
            if (rowB < n) {
                __half2 v = __floats2half2_rn(acc[mf][nf][2] * dB, acc[mf][nf][3] * dB);
                *(__half2*)(Y + (size_t)rowB * wcols + col) = v;
            }
        }
    }
}

// ---------------------------------------------------------------------------
// fp16 8-channel accumulate: acc += w * v (v = 8 halves in uint4)
__device__ __forceinline__ void acc8w(float* acc, float w, uint4 r) {
    float2 f0 = __half22float2(*(__half2*)&r.x);
    float2 f1 = __half22float2(*(__half2*)&r.y);
    float2 f2 = __half22float2(*(__half2*)&r.z);
    float2 f3 = __half22float2(*(__half2*)&r.w);
    acc[0] = fmaf(w, f0.x, acc[0]); acc[1] = fmaf(w, f0.y, acc[1]);
    acc[2] = fmaf(w, f1.x, acc[2]); acc[3] = fmaf(w, f1.y, acc[3]);
    acc[4] = fmaf(w, f2.x, acc[4]); acc[5] = fmaf(w, f2.y, acc[5]);
    acc[6] = fmaf(w, f3.x, acc[6]); acc[7] = fmaf(w, f3.y, acc[7]);
}
// fp16 8-channel accumulate (no weight)
__device__ __forceinline__ void acc8s(float* acc, uint4 r) {
    float2 f0 = __half22float2(*(__half2*)&r.x);
    float2 f1 = __half22float2(*(__half2*)&r.y);
    float2 f2 = __half22float2(*(__half2*)&r.z);
    float2 f3 = __half22float2(*(__half2*)&r.w);
    acc[0] += f0.x; acc[1] += f0.y;
    acc[2] += f1.x; acc[3] += f1.y;
    acc[4] += f2.x; acc[5] += f2.y;
    acc[6] += f3.x; acc[7] += f3.y;
}

// Layer-1 aggregation: TWO nodes per warp, each owned by a 16-lane half-warp
// (uint4 = 8 ch/lane, 128 ch total). Unroll 4.
__global__ void k_aggA(const float* __restrict__ b1, int n) {
    int g = blockIdx.x * blockDim.x + threadIdx.x;
    int node = g >> 4;
    int l = g & 15;
    if (node >= n) return;
    const size_t chOff = (size_t)l * 8;
    int end = g_incl[node];
    int p = end - g_cnt[node];
    float acc[8] = {0.f, 0.f, 0.f, 0.f, 0.f, 0.f, 0.f, 0.f};
    for (; p + 4 <= end; p += 4) {
        int s0 = g_csrc[p], s1 = g_csrc[p + 1], s2 = g_csrc[p + 2], s3 = g_csrc[p + 3];
        float w0 = g_dis[s0], w1 = g_dis[s1], w2 = g_dis[s2], w3 = g_dis[s3];
        uint4 r0 = *(const uint4*)(g_h1 + (size_t)s0 * CH + chOff);
        uint4 r1 = *(const uint4*)(g_h1 + (size_t)s1 * CH + chOff);
        uint4 r2 = *(const uint4*)(g_h1 + (size_t)s2 * CH + chOff);
        uint4 r3 = *(const uint4*)(g_h1 + (size_t)s3 * CH + chOff);
        acc8w(acc, w0, r0); acc8w(acc, w1, r1); acc8w(acc, w2, r2); acc8w(acc, w3, r3);
    }
    for (; p < end; ++p) {
        int s = g_csrc[p];
        acc8w(acc, g_dis[s], *(const uint4*)(g_h1 + (size_t)s * CH + chOff));
    }
    float di = g_dis[node];
    acc8w(acc, di, *(const uint4*)(g_h1 + (size_t)node * CH + chOff));
    float4 ba = ((const float4*)b1)[l * 2];
    float4 bb = ((const float4*)b1)[l * 2 + 1];
    float o0 = fmaxf(fmaf(di, acc[0], ba.x), 0.f);
    float o1 = fmaxf(fmaf(di, acc[1], ba.y), 0.f);
    float o2 = fmaxf(fmaf(di, acc[2], ba.z), 0.f);
    float o3 = fmaxf(fmaf(di, acc[3], ba.w), 0.f);
    float o4 = fmaxf(fmaf(di, acc[4], bb.x), 0.f);
    float o5 = fmaxf(fmaf(di, acc[5], bb.y), 0.f);
    float o6 = fmaxf(fmaf(di, acc[6], bb.z), 0.f);
    float o7 = fmaxf(fmaf(di, acc[7], bb.w), 0.f);
    uint4 w;
    *(__half2*)&w.x = __floats2half2_rn(o0, o1);
    *(__half2*)&w.y = __floats2half2_rn(o2, o3);
    *(__half2*)&w.z = __floats2half2_rn(o4, o5);
    *(__half2*)&w.w = __floats2half2_rn(o6, o7);
    *(uint4*)(g_h + (size_t)node * CH + chOff) = w;
}

// Layer-2 aggregation: 5 lanes x uint4 (8 ch) = exactly 40 ch per node.
// h2s pre-scaled by dis; fused self-loop + bias; fp32 out. Unroll 4.
__global__ void k_aggB(const float* __restrict__ b2, float* __restrict__ out, int n) {
    int g = blockIdx.x * blockDim.x + threadIdx.x;
    int node = g / 5, l = g % 5;
    if (node >= n) return;
    const size_t chOff = (size_t)l * 8;
    int end = g_incl[node];
    int p = end - g_cnt[node];
    float acc[8] = {0.f, 0.f, 0.f, 0.f, 0.f, 0.f, 0.f, 0.f};
    for (; p + 4 <= end; p += 4) {
        int s0 = g_csrc[p], s1 = g_csrc[p + 1], s2 = g_csrc[p + 2], s3 = g_csrc[p + 3];
        uint4 r0 = *(const uint4*)(g_h2s + (size_t)s0 * COUT + chOff);
        uint4 r1 = *(const uint4*)(g_h2s + (size_t)s1 * COUT + chOff);
        uint4 r2 = *(const uint4*)(g_h2s + (size_t)s2 * COUT + chOff);
        uint4 r3 = *(const uint4*)(g_h2s + (size_t)s3 * COUT + chOff);
        acc8s(acc, r0); acc8s(acc, r1); acc8s(acc, r2); acc8s(acc, r3);
    }
    for (; p < end; ++p) {
        int s = g_csrc[p];
        acc8s(acc, *(const uint4*)(g_h2s + (size_t)s * COUT + chOff));
    }
    acc8s(acc, *(const uint4*)(g_h2s + (size_t)node * COUT + chOff));
    float di = g_dis[node];
    float4 ba = *(const float4*)(b2 + l * 8);
    float4 bb = *(const float4*)(b2 + l * 8 + 4);
    float4 r0, r1;
    r0.x = fmaf(di, acc[0], ba.x);
    r0.y = fmaf(di, acc[1], ba.y);
    r0.z = fmaf(di, acc[2], ba.z);
    r0.w = fmaf(di, acc[3], ba.w);
    r1.x = fmaf(di, acc[4], bb.x);
    r1.y = fmaf(di, acc[5], bb.y);
    r1.z = fmaf(di, acc[6], bb.z);
    r1.w = fmaf(di, acc[7], bb.w);
    *(float4*)(out + (size_t)node * COUT + l * 8) = r0;
    *(float4*)(out + (size_t)node * COUT + l * 8 + 4) = r1;
}

// ---------------------------------------------------------------------------
extern "C" void kernel_launch(void* const* d_in, const int* in_sizes, int n_in,
                              void* d_out, int out_size) {
    const float* x  = (const float*)d_in[0];
    const float* W1 = (const float*)d_in[1];
    const float* b1 = (const float*)d_in[2];
    const float* W2 = (const float*)d_in[3];
    const float* b2 = (const float*)d_in[4];
    const int* edge = (const int*)d_in[5];

    const int n = in_sizes[0] / CIN;
    const int e = in_sizes[5] / 2;
    const int* src = edge;
    const int* dst = edge + e;
    float* out = (float*)d_out;

    __half *p_h1 = nullptr, *p_h = nullptr, *p_h2s = nullptr;
    __half *p_w1h = nullptr, *p_w2h = nullptr;
    void *p_cnt = nullptr, *p_flag = nullptr;
    cudaGetSymbolAddress((void**)&p_h1, g_h1);
    cudaGetSymbolAddress((void**)&p_h, g_h);
    cudaGetSymbolAddress((void**)&p_h2s, g_h2s);
    cudaGetSymbolAddress((void**)&p_w1h, g_w1h);
    cudaGetSymbolAddress((void**)&p_w2h, g_w2h);
    cudaGetSymbolAddress(&p_cnt, g_cnt);
    cudaGetSymbolAddress(&p_flag, (const void*)g_flag);

    const int smem1 = (64 * KS + 128 * KS) * 2;  // 52224 B -> 4 CTAs/SM
    const int smem2 = (64 * KS + 64 * KS) * 2;   // 34816 B -> 6 CTAs/SM
    cudaFuncSetAttribute(k_mma<128, false, float>, cudaFuncAttributeMaxDynamicSharedMemorySize, smem1);
    cudaFuncSetAttribute(k_mma<64, true, __half>,  cudaFuncAttributeMaxDynamicSharedMemorySize, smem2);

    static cudaStream_t s1 = nullptr, s2 = nullptr;
    static cudaEvent_t evFork = nullptr, evJoin = nullptr, evDone = nullptr;
    if (s1 == nullptr) {
        cudaStreamCreateWithFlags(&s1, cudaStreamNonBlocking);
        cudaStreamCreateWithFlags(&s2, cudaStreamNonBlocking);
        cudaEventCreateWithFlags(&evFork, cudaEventDisableTiming);
        cudaEventCreateWithFlags(&evJoin, cudaEventDisableTiming);
        cudaEventCreateWithFlags(&evDone, cudaEventDisableTiming);
    }

    // Fork into s1 (GEMM chain) and s2 (CSR).
    cudaEventRecord(evFork, 0);
    cudaStreamWaitEvent(s1, evFork, 0);
    cudaStreamWaitEvent(s2, evFork, 0);

    // CSR branch (latency-bound; overlaps with GEMM1)
    cudaMemsetAsync(p_cnt, 0, (size_t)n * sizeof(int), s2);
    cudaMemsetAsync(p_flag, 0, (size_t)NBLK * sizeof(int), s2);
    k_hist<<<(e + 255) / 256, 256, 0, s2>>>(dst, e);
    k_scanDL<<<NBLK, SCAN_B, 0, s2>>>(n);
    k_scatter<<<(e + 255) / 256, 256, 0, s2>>>(src, dst, e);
    cudaEventRecord(evJoin, s2);

    // GEMM branch: W pre-convert, then GEMM1
    k_wconv<<<(128 * 128 + 64 * 128 + 255) / 256, 256, 0, s1>>>(W1, W2);
    k_mma<128, false, float><<<(n + 63) / 64, 256, smem1, s1>>>(x, p_w1h, 128, p_h1, n);

    // Join: aggregation needs CSR + dis + h1
    cudaStreamWaitEvent(s1, evJoin, 0);
    k_aggA<<<(int)(((size_t)n * 16 + 255) / 256), 256, 0, s1>>>(b1, n);

    // layer 2 (GEMM first: aggregate only 40 channels)
    k_mma<64, true, __half><<<(n + 63) / 64, 256, smem2, s1>>>(p_h, p_w2h, COUT, p_h2s, n);
    k_aggB<<<(int)(((size_t)n * 5 + 319) / 320), 320, 0, s1>>>(b2, out, n);

    // Join back to the launch stream.
    cudaEventRecord(evDone, s1);
    cudaStreamWaitEvent(0, evDone, 0);
}